// round 1
// baseline (speedup 1.0000x reference)
#include <cuda_runtime.h>
#include <cuda_bf16.h>
#include <math.h>

#define T_TOK 2048
#define D_DIM 1152
#define H_NUM 16
#define DH 72
#define NCU 9

// ---------------- scratch (no allocations allowed) ----------------
__device__ float g_q[T_TOK * D_DIM];
__device__ float g_k[T_TOK * D_DIM];
__device__ float g_v[T_TOK * D_DIM];
__device__ float g_attn[T_TOK * D_DIM];

// ---------------- SGEMM: C[M,N] = A[M,K] @ B[N,K]^T + bias[N] ----------------
// BM=BN=128, BK=16, 256 threads, 8x8 per thread, double-buffered smem.
#define BM 128
#define BN 128
#define BK 16

__global__ __launch_bounds__(256) void sgemm_nt_bias(
    const float* __restrict__ A, const float* __restrict__ Bw,
    const float* __restrict__ bias, float* __restrict__ C,
    int M, int N, int K)
{
    __shared__ float As[2][BK][BM];
    __shared__ float Bs[2][BK][BN];
    const int tid = threadIdx.x;
    const int bm = blockIdx.y * BM;
    const int bn = blockIdx.x * BN;

    const int lr = tid >> 2;          // 0..63
    const int lc = (tid & 3) * 4;     // 0,4,8,12

    const float* Aptr = A + (size_t)bm * K;
    const float* Bptr = Bw + (size_t)bn * K;

    const int ty = tid >> 4;          // 0..15
    const int tx = tid & 15;          // 0..15

    float acc[8][8];
#pragma unroll
    for (int i = 0; i < 8; i++)
#pragma unroll
        for (int j = 0; j < 8; j++) acc[i][j] = 0.f;

    auto load_tile = [&](int buf, int k0) {
#pragma unroll
        for (int r = 0; r < 2; r++) {
            int row = lr + r * 64;
            float4 av = *(const float4*)(Aptr + (size_t)row * K + k0 + lc);
            As[buf][lc + 0][row] = av.x;
            As[buf][lc + 1][row] = av.y;
            As[buf][lc + 2][row] = av.z;
            As[buf][lc + 3][row] = av.w;
            float4 bv = *(const float4*)(Bptr + (size_t)row * K + k0 + lc);
            Bs[buf][lc + 0][row] = bv.x;
            Bs[buf][lc + 1][row] = bv.y;
            Bs[buf][lc + 2][row] = bv.z;
            Bs[buf][lc + 3][row] = bv.w;
        }
    };

    load_tile(0, 0);
    __syncthreads();

    const int nk = K / BK;
    for (int kt = 0; kt < nk; kt++) {
        int buf = kt & 1;
        if (kt + 1 < nk) load_tile(buf ^ 1, (kt + 1) * BK);
#pragma unroll
        for (int k = 0; k < BK; k++) {
            float a[8], b[8];
#pragma unroll
            for (int i = 0; i < 8; i++) a[i] = As[buf][k][ty * 8 + i];
#pragma unroll
            for (int j = 0; j < 8; j++) b[j] = Bs[buf][k][tx * 8 + j];
#pragma unroll
            for (int i = 0; i < 8; i++)
#pragma unroll
                for (int j = 0; j < 8; j++) acc[i][j] += a[i] * b[j];
        }
        __syncthreads();
    }

#pragma unroll
    for (int i = 0; i < 8; i++) {
        int m = bm + ty * 8 + i;
#pragma unroll
        for (int j = 0; j < 8; j += 4) {
            int n = bn + tx * 8 + j;
            float4 o;
            o.x = acc[i][j + 0] + bias[n + 0];
            o.y = acc[i][j + 1] + bias[n + 1];
            o.z = acc[i][j + 2] + bias[n + 2];
            o.w = acc[i][j + 3] + bias[n + 3];
            *(float4*)(C + (size_t)m * N + n) = o;
        }
    }
}

// ---------------- RoPE (in-place on q and k) ----------------
__global__ void rope_kernel(float* __restrict__ q, float* __restrict__ k,
                            const float* __restrict__ cosp,
                            const float* __restrict__ sinp)
{
    int idx = blockIdx.x * blockDim.x + threadIdx.x;
    const int total = T_TOK * H_NUM * (DH / 2);
    if (idx >= total) return;
    int d = idx % (DH / 2);
    int th = idx / (DH / 2);
    int h = th % H_NUM;
    int t = th / H_NUM;

    float c = cosp[t * DH + d];
    float s = sinp[t * DH + d];
    size_t base = (size_t)t * D_DIM + h * DH;

    float q1 = q[base + d], q2 = q[base + d + DH / 2];
    q[base + d]          = q1 * c - q2 * s;
    q[base + d + DH / 2] = q2 * c + q1 * s;

    float k1 = k[base + d], k2 = k[base + d + DH / 2];
    k[base + d]          = k1 * c - k2 * s;
    k[base + d + DH / 2] = k2 * c + k1 * s;
}

// ---------------- Segment-masked flash attention ----------------
// grid: (T/64, H). 256 threads: thread = (qrow = tid>>2, cpart = tid&3).
// Each thread owns 18 output dims of one query row; S columns interleaved
// kk = cpart + 4*j for conflict-free sK reads.
#define QT 64
#define KT 64
#define SS_STRIDE 68   // padded so sS writes are conflict-free

__global__ __launch_bounds__(256) void attn_kernel(
    const float* __restrict__ q, const float* __restrict__ k,
    const float* __restrict__ v, const int* __restrict__ cu,
    float* __restrict__ out)
{
    extern __shared__ float smem[];
    float* sQ = smem;                 // 64*72
    float* sK = sQ + QT * DH;         // 64*72
    float* sV = sK + KT * DH;         // 64*72
    float* sS = sV + KT * DH;         // 64*68
    __shared__ int sCu[NCU];
    __shared__ int sSegQ[QT];

    const int tid = threadIdx.x;
    const int h = blockIdx.y;
    const int q0 = blockIdx.x * QT;

    if (tid < NCU) sCu[tid] = cu[tid];
    __syncthreads();

    const float scale = rsqrtf((float)DH);
    for (int i = tid; i < QT * DH; i += 256) {
        int r = i / DH, c = i % DH;
        sQ[i] = q[(size_t)(q0 + r) * D_DIM + h * DH + c] * scale;
    }
    if (tid < QT) {
        int t = q0 + tid;
        int s = 0;
#pragma unroll
        for (int j = 1; j < NCU; j++)
            if (sCu[j] <= t) s = j;
        sSegQ[tid] = s;
    }
    __syncthreads();

    const int seg_lo = sSegQ[0];
    const int seg_hi = sSegQ[QT - 1];
    const int k_end = sCu[seg_hi + 1];
    const int kc0 = (sCu[seg_lo] / KT) * KT;

    const int qrow = tid >> 2;
    const int cpart = tid & 3;
    const int segq = sSegQ[qrow];

    float m_i = -1e30f, l_i = 0.f;
    float O[18];
#pragma unroll
    for (int i = 0; i < 18; i++) O[i] = 0.f;

    for (int kc = kc0; kc < k_end; kc += KT) {
        for (int i = tid; i < KT * DH; i += 256) {
            int r = i / DH, c = i % DH;
            sK[i] = k[(size_t)(kc + r) * D_DIM + h * DH + c];
            sV[i] = v[(size_t)(kc + r) * D_DIM + h * DH + c];
        }
        __syncthreads();

        // scores: 16 interleaved columns per thread
        float sv[16];
        const float4* qp = (const float4*)(sQ + qrow * DH);
#pragma unroll
        for (int j = 0; j < 16; j++) {
            int kk = cpart + 4 * j;
            int kg = kc + kk;
            int segk = 0;
#pragma unroll
            for (int s2 = 1; s2 < NCU; s2++)
                if (sCu[s2] <= kg) segk = s2;
            const float4* kp = (const float4*)(sK + kk * DH);
            float acc = 0.f;
#pragma unroll
            for (int c4 = 0; c4 < DH / 4; c4++) {
                float4 a = qp[c4], b = kp[c4];
                acc += a.x * b.x + a.y * b.y + a.z * b.z + a.w * b.w;
            }
            sv[j] = (segk == segq) ? acc : -1e30f;
        }

        // online softmax (row shared by 4 consecutive lanes)
        float mloc = -1e30f;
#pragma unroll
        for (int j = 0; j < 16; j++) mloc = fmaxf(mloc, sv[j]);
        mloc = fmaxf(mloc, __shfl_xor_sync(0xffffffffu, mloc, 1));
        mloc = fmaxf(mloc, __shfl_xor_sync(0xffffffffu, mloc, 2));
        float m_new = fmaxf(m_i, mloc);

        float lloc = 0.f;
#pragma unroll
        for (int j = 0; j < 16; j++) {
            float p = (sv[j] < -1e29f) ? 0.f : __expf(sv[j] - m_new);
            sv[j] = p;
            lloc += p;
        }
        lloc += __shfl_xor_sync(0xffffffffu, lloc, 1);
        lloc += __shfl_xor_sync(0xffffffffu, lloc, 2);

        float alpha = __expf(m_i - m_new);
        l_i = l_i * alpha + lloc;
        m_i = m_new;
#pragma unroll
        for (int i = 0; i < 18; i++) O[i] *= alpha;

        // share P within warp via padded smem
#pragma unroll
        for (int j = 0; j < 16; j++)
            sS[qrow * SS_STRIDE + cpart + 4 * j] = sv[j];
        __syncwarp();

        // O += P @ V  (thread owns cols [cpart*18, cpart*18+18))
        for (int kk = 0; kk < KT; kk++) {
            float pp = sS[qrow * SS_STRIDE + kk];
            const float2* vp = (const float2*)(sV + kk * DH + cpart * 18);
#pragma unroll
            for (int c2 = 0; c2 < 9; c2++) {
                float2 vv = vp[c2];
                O[2 * c2 + 0] += pp * vv.x;
                O[2 * c2 + 1] += pp * vv.y;
            }
        }
        __syncthreads();
    }

    float inv_l = 1.f / l_i;
    size_t obase = (size_t)(q0 + qrow) * D_DIM + h * DH + cpart * 18;
#pragma unroll
    for (int c = 0; c < 18; c++) out[obase + c] = O[c] * inv_l;
}

// ---------------- host launch ----------------
extern "C" void kernel_launch(void* const* d_in, const int* in_sizes, int n_in,
                              void* d_out, int out_size)
{
    const float* hs   = (const float*)d_in[0];
    const int*   cu   = (const int*)  d_in[1];
    const float* cosp = (const float*)d_in[2];
    const float* sinp = (const float*)d_in[3];
    const float* Wq   = (const float*)d_in[4];
    const float* bq   = (const float*)d_in[5];
    const float* Wk   = (const float*)d_in[6];
    const float* bk   = (const float*)d_in[7];
    const float* Wv   = (const float*)d_in[8];
    const float* bv   = (const float*)d_in[9];
    const float* Wo   = (const float*)d_in[10];
    const float* bo   = (const float*)d_in[11];
    float* out = (float*)d_out;

    float *q, *k, *v, *attn;
    cudaGetSymbolAddress((void**)&q, g_q);
    cudaGetSymbolAddress((void**)&k, g_k);
    cudaGetSymbolAddress((void**)&v, g_v);
    cudaGetSymbolAddress((void**)&attn, g_attn);

    dim3 gemm_grid(D_DIM / BN, T_TOK / BM);
    sgemm_nt_bias<<<gemm_grid, 256>>>(hs, Wq, bq, q, T_TOK, D_DIM, D_DIM);
    sgemm_nt_bias<<<gemm_grid, 256>>>(hs, Wk, bk, k, T_TOK, D_DIM, D_DIM);
    sgemm_nt_bias<<<gemm_grid, 256>>>(hs, Wv, bv, v, T_TOK, D_DIM, D_DIM);

    int rope_total = T_TOK * H_NUM * (DH / 2);
    rope_kernel<<<(rope_total + 255) / 256, 256>>>(q, k, cosp, sinp);

    int attn_smem = (3 * QT * DH + QT * SS_STRIDE) * (int)sizeof(float);
    cudaFuncSetAttribute(attn_kernel,
                         cudaFuncAttributeMaxDynamicSharedMemorySize, attn_smem);
    attn_kernel<<<dim3(T_TOK / QT, H_NUM), 256, attn_smem>>>(q, k, v, cu, attn);

    sgemm_nt_bias<<<gemm_grid, 256>>>(attn, Wo, bo, out, T_TOK, D_DIM, D_DIM);
}

// round 4
// speedup vs baseline: 2.4816x; 2.4816x over previous
#include <cuda_runtime.h>
#include <cuda_bf16.h>
#include <cstdint>
#include <math.h>

#define T_TOK 2048
#define D_DIM 1152
#define H_NUM 16
#define DH 72
#define NCU 9

// ---------------- scratch (no allocations allowed) ----------------
__device__ float g_q[T_TOK * D_DIM];
__device__ float g_k[T_TOK * D_DIM];
__device__ float g_v[T_TOK * D_DIM];
__device__ float g_attn[T_TOK * D_DIM];

__device__ __forceinline__ float to_tf32(float x) {
    float y; asm("cvt.rna.tf32.f32 %0, %1;" : "=f"(y) : "f"(x)); return y;
}

__device__ __forceinline__ void mma_tf32(float& d0, float& d1, float& d2, float& d3,
                                         uint32_t a0, uint32_t a1, uint32_t a2, uint32_t a3,
                                         uint32_t b0, uint32_t b1) {
    asm volatile(
        "mma.sync.aligned.m16n8k8.row.col.f32.tf32.tf32.f32 "
        "{%0,%1,%2,%3}, {%4,%5,%6,%7}, {%8,%9}, {%0,%1,%2,%3};"
        : "+f"(d0), "+f"(d1), "+f"(d2), "+f"(d3)
        : "r"(a0), "r"(a1), "r"(a2), "r"(a3), "r"(b0), "r"(b1));
}

// ================= tf32 mma.sync GEMM: C[M,N] = A[M,K] @ W[N,K]^T + bias =================
// CTA tile 128x128, K-chunk 16, 8 warps (2x4), warp tile 64x32.
#define KCH 16
#define NCHUNK (D_DIM / KCH)   // 72
#define SPAD 20                // floats per smem row (16 + 4 pad), 16B aligned

__global__ __launch_bounds__(256) void gemm_tf32_nt_bias(
    const float* __restrict__ A, const float* __restrict__ Bw,
    const float* __restrict__ bias, float* __restrict__ C)
{
    __shared__ float sA[2][128 * SPAD];
    __shared__ float sB[2][128 * SPAD];

    const int tid = threadIdx.x;
    const int wid = tid >> 5;
    const int lane = tid & 31;
    const int gid = lane >> 2;     // 0..7
    const int tig = lane & 3;      // 0..3
    const int wm = wid >> 2;       // 0..1  (64-row slab)
    const int wn = wid & 3;        // 0..3  (32-col slab)

    const int bm = blockIdx.y * 128;
    const int bn = blockIdx.x * 128;

    // loader mapping: 2 threads per row, each loads 2 float4 (8 floats)
    const int lrow = tid >> 1;         // 0..127
    const int lpart = (tid & 1) * 8;   // 0 or 8
    const float* Ag = A + (size_t)(bm + lrow) * D_DIM + lpart;
    const float* Bg = Bw + (size_t)(bn + lrow) * D_DIM + lpart;

    float4 pa0, pa1, pb0, pb1;

    auto prefetch = [&](int c) {
        const float* ag = Ag + c * KCH;
        const float* bg = Bg + c * KCH;
        pa0 = *(const float4*)(ag);
        pa1 = *(const float4*)(ag + 4);
        pb0 = *(const float4*)(bg);
        pb1 = *(const float4*)(bg + 4);
    };
    auto store_chunk = [&](int buf) {
        float4 v;
        v.x = to_tf32(pa0.x); v.y = to_tf32(pa0.y); v.z = to_tf32(pa0.z); v.w = to_tf32(pa0.w);
        *(float4*)(&sA[buf][lrow * SPAD + lpart]) = v;
        v.x = to_tf32(pa1.x); v.y = to_tf32(pa1.y); v.z = to_tf32(pa1.z); v.w = to_tf32(pa1.w);
        *(float4*)(&sA[buf][lrow * SPAD + lpart + 4]) = v;
        v.x = to_tf32(pb0.x); v.y = to_tf32(pb0.y); v.z = to_tf32(pb0.z); v.w = to_tf32(pb0.w);
        *(float4*)(&sB[buf][lrow * SPAD + lpart]) = v;
        v.x = to_tf32(pb1.x); v.y = to_tf32(pb1.y); v.z = to_tf32(pb1.z); v.w = to_tf32(pb1.w);
        *(float4*)(&sB[buf][lrow * SPAD + lpart + 4]) = v;
    };

    float acc[4][4][4];
#pragma unroll
    for (int i = 0; i < 4; i++)
#pragma unroll
        for (int j = 0; j < 4; j++)
#pragma unroll
            for (int r = 0; r < 4; r++) acc[i][j][r] = 0.f;

    prefetch(0);
    store_chunk(0);
    __syncthreads();

    const uint32_t* uA;
    const uint32_t* uB;

    for (int c = 0; c < NCHUNK; c++) {
        const int buf = c & 1;
        if (c + 1 < NCHUNK) prefetch(c + 1);

        uA = (const uint32_t*)sA[buf];
        uB = (const uint32_t*)sB[buf];

#pragma unroll
        for (int ks = 0; ks < 2; ks++) {
            const int k0 = ks * 8;
            uint32_t af[4][4], bf[4][2];
#pragma unroll
            for (int ma = 0; ma < 4; ma++) {
                int r0 = (wm * 64 + ma * 16 + gid) * SPAD;
                af[ma][0] = uA[r0 + k0 + tig];
                af[ma][1] = uA[r0 + 8 * SPAD + k0 + tig];
                af[ma][2] = uA[r0 + k0 + tig + 4];
                af[ma][3] = uA[r0 + 8 * SPAD + k0 + tig + 4];
            }
#pragma unroll
            for (int na = 0; na < 4; na++) {
                int r0 = (wn * 32 + na * 8 + gid) * SPAD;
                bf[na][0] = uB[r0 + k0 + tig];
                bf[na][1] = uB[r0 + k0 + tig + 4];
            }
#pragma unroll
            for (int ma = 0; ma < 4; ma++)
#pragma unroll
                for (int na = 0; na < 4; na++)
                    mma_tf32(acc[ma][na][0], acc[ma][na][1], acc[ma][na][2], acc[ma][na][3],
                             af[ma][0], af[ma][1], af[ma][2], af[ma][3],
                             bf[na][0], bf[na][1]);
        }

        if (c + 1 < NCHUNK) store_chunk(buf ^ 1);
        __syncthreads();
    }

    // epilogue: D layout — c0:(gid, tig*2) c1:(gid, tig*2+1) c2/c3: row+8
#pragma unroll
    for (int ma = 0; ma < 4; ma++) {
        int row = bm + wm * 64 + ma * 16 + gid;
#pragma unroll
        for (int na = 0; na < 4; na++) {
            int col = bn + wn * 32 + na * 8 + tig * 2;
            float2 bb = *(const float2*)(bias + col);
            float2 o0, o1;
            o0.x = acc[ma][na][0] + bb.x;
            o0.y = acc[ma][na][1] + bb.y;
            o1.x = acc[ma][na][2] + bb.x;
            o1.y = acc[ma][na][3] + bb.y;
            *(float2*)(C + (size_t)row * D_DIM + col) = o0;
            *(float2*)(C + (size_t)(row + 8) * D_DIM + col) = o1;
        }
    }
}

// ---------------- RoPE (in-place on q and k) ----------------
__global__ void rope_kernel(float* __restrict__ q, float* __restrict__ k,
                            const float* __restrict__ cosp,
                            const float* __restrict__ sinp)
{
    int idx = blockIdx.x * blockDim.x + threadIdx.x;
    const int total = T_TOK * H_NUM * (DH / 2);
    if (idx >= total) return;
    int d = idx % (DH / 2);
    int th = idx / (DH / 2);
    int h = th % H_NUM;
    int t = th / H_NUM;

    float c = cosp[t * DH + d];
    float s = sinp[t * DH + d];
    size_t base = (size_t)t * D_DIM + h * DH;

    float q1 = q[base + d], q2 = q[base + d + DH / 2];
    q[base + d]          = q1 * c - q2 * s;
    q[base + d + DH / 2] = q2 * c + q1 * s;

    float k1 = k[base + d], k2 = k[base + d + DH / 2];
    k[base + d]          = k1 * c - k2 * s;
    k[base + d + DH / 2] = k2 * c + k1 * s;
}

// ---------------- Segment-masked flash attention (fp32 SIMT) ----------------
#define QT 64
#define KT 64
#define SS_STRIDE 68

__global__ __launch_bounds__(256) void attn_kernel(
    const float* __restrict__ q, const float* __restrict__ k,
    const float* __restrict__ v, const int* __restrict__ cu,
    float* __restrict__ out)
{
    extern __shared__ float smemf[];
    float* sQ = smemf;
    float* sK = sQ + QT * DH;
    float* sV = sK + KT * DH;
    float* sS = sV + KT * DH;
    __shared__ int sCu[NCU];
    __shared__ int sSegQ[QT];

    const int tid = threadIdx.x;
    const int h = blockIdx.y;
    const int q0 = blockIdx.x * QT;

    if (tid < NCU) sCu[tid] = cu[tid];
    __syncthreads();

    const float scale = rsqrtf((float)DH);
    for (int i = tid; i < QT * DH; i += 256) {
        int r = i / DH, c = i % DH;
        sQ[i] = q[(size_t)(q0 + r) * D_DIM + h * DH + c] * scale;
    }
    if (tid < QT) {
        int t = q0 + tid;
        int s = 0;
#pragma unroll
        for (int j = 1; j < NCU; j++)
            if (sCu[j] <= t) s = j;
        sSegQ[tid] = s;
    }
    __syncthreads();

    const int seg_lo = sSegQ[0];
    const int seg_hi = sSegQ[QT - 1];
    const int k_end = sCu[seg_hi + 1];
    const int kc0 = (sCu[seg_lo] / KT) * KT;

    const int qrow = tid >> 2;
    const int cpart = tid & 3;
    const int segq = sSegQ[qrow];

    float m_i = -1e30f, l_i = 0.f;
    float O[18];
#pragma unroll
    for (int i = 0; i < 18; i++) O[i] = 0.f;

    for (int kc = kc0; kc < k_end; kc += KT) {
        for (int i = tid; i < KT * DH; i += 256) {
            int r = i / DH, c = i % DH;
            sK[i] = k[(size_t)(kc + r) * D_DIM + h * DH + c];
            sV[i] = v[(size_t)(kc + r) * D_DIM + h * DH + c];
        }
        __syncthreads();

        float sv[16];
        const float4* qp = (const float4*)(sQ + qrow * DH);
#pragma unroll
        for (int j = 0; j < 16; j++) {
            int kk = cpart + 4 * j;
            int kg = kc + kk;
            int segk = 0;
#pragma unroll
            for (int s2 = 1; s2 < NCU; s2++)
                if (sCu[s2] <= kg) segk = s2;
            const float4* kp = (const float4*)(sK + kk * DH);
            float acc = 0.f;
#pragma unroll
            for (int c4 = 0; c4 < DH / 4; c4++) {
                float4 a = qp[c4], b = kp[c4];
                acc += a.x * b.x + a.y * b.y + a.z * b.z + a.w * b.w;
            }
            sv[j] = (segk == segq) ? acc : -1e30f;
        }

        float mloc = -1e30f;
#pragma unroll
        for (int j = 0; j < 16; j++) mloc = fmaxf(mloc, sv[j]);
        mloc = fmaxf(mloc, __shfl_xor_sync(0xffffffffu, mloc, 1));
        mloc = fmaxf(mloc, __shfl_xor_sync(0xffffffffu, mloc, 2));
        float m_new = fmaxf(m_i, mloc);

        float lloc = 0.f;
#pragma unroll
        for (int j = 0; j < 16; j++) {
            float p = (sv[j] < -1e29f) ? 0.f : __expf(sv[j] - m_new);
            sv[j] = p;
            lloc += p;
        }
        lloc += __shfl_xor_sync(0xffffffffu, lloc, 1);
        lloc += __shfl_xor_sync(0xffffffffu, lloc, 2);

        float alpha = __expf(m_i - m_new);
        l_i = l_i * alpha + lloc;
        m_i = m_new;
#pragma unroll
        for (int i = 0; i < 18; i++) O[i] *= alpha;

#pragma unroll
        for (int j = 0; j < 16; j++)
            sS[qrow * SS_STRIDE + cpart + 4 * j] = sv[j];
        __syncwarp();

        for (int kk = 0; kk < KT; kk++) {
            float pp = sS[qrow * SS_STRIDE + kk];
            const float2* vp = (const float2*)(sV + kk * DH + cpart * 18);
#pragma unroll
            for (int c2 = 0; c2 < 9; c2++) {
                float2 vv = vp[c2];
                O[2 * c2 + 0] += pp * vv.x;
                O[2 * c2 + 1] += pp * vv.y;
            }
        }
        __syncthreads();
    }

    float inv_l = 1.f / l_i;
    size_t obase = (size_t)(q0 + qrow) * D_DIM + h * DH + cpart * 18;
#pragma unroll
    for (int c = 0; c < 18; c++) out[obase + c] = O[c] * inv_l;
}

// ---------------- host launch ----------------
extern "C" void kernel_launch(void* const* d_in, const int* in_sizes, int n_in,
                              void* d_out, int out_size)
{
    const float* hs   = (const float*)d_in[0];
    const int*   cu   = (const int*)  d_in[1];
    const float* cosp = (const float*)d_in[2];
    const float* sinp = (const float*)d_in[3];
    const float* Wq   = (const float*)d_in[4];
    const float* bq   = (const float*)d_in[5];
    const float* Wk   = (const float*)d_in[6];
    const float* bk   = (const float*)d_in[7];
    const float* Wv   = (const float*)d_in[8];
    const float* bv   = (const float*)d_in[9];
    const float* Wo   = (const float*)d_in[10];
    const float* bo   = (const float*)d_in[11];
    float* out = (float*)d_out;

    float *q, *k, *v, *attn;
    cudaGetSymbolAddress((void**)&q, g_q);
    cudaGetSymbolAddress((void**)&k, g_k);
    cudaGetSymbolAddress((void**)&v, g_v);
    cudaGetSymbolAddress((void**)&attn, g_attn);

    dim3 gemm_grid(D_DIM / 128, T_TOK / 128);  // (9, 16)
    gemm_tf32_nt_bias<<<gemm_grid, 256>>>(hs, Wq, bq, q);
    gemm_tf32_nt_bias<<<gemm_grid, 256>>>(hs, Wk, bk, k);
    gemm_tf32_nt_bias<<<gemm_grid, 256>>>(hs, Wv, bv, v);

    int rope_total = T_TOK * H_NUM * (DH / 2);
    rope_kernel<<<(rope_total + 255) / 256, 256>>>(q, k, cosp, sinp);

    int attn_smem = (3 * QT * DH + QT * SS_STRIDE) * (int)sizeof(float);
    cudaFuncSetAttribute(attn_kernel,
                         cudaFuncAttributeMaxDynamicSharedMemorySize, attn_smem);
    attn_kernel<<<dim3(T_TOK / QT, H_NUM), 256, attn_smem>>>(q, k, v, cu, attn);

    gemm_tf32_nt_bias<<<gemm_grid, 256>>>(attn, Wo, bo, out);
}

// round 5
// speedup vs baseline: 4.1946x; 1.6903x over previous
#include <cuda_runtime.h>
#include <cuda_bf16.h>
#include <cstdint>
#include <math.h>

#define T_TOK 2048
#define D_DIM 1152
#define H_NUM 16
#define DH 72
#define NCU 9

// ---------------- scratch (no allocations allowed) ----------------
__device__ float g_q[T_TOK * D_DIM];
__device__ float g_k[T_TOK * D_DIM];
__device__ float g_v[T_TOK * D_DIM];
__device__ float g_attn[T_TOK * D_DIM];

__device__ __forceinline__ float to_tf32(float x) {
    float y; asm("cvt.rna.tf32.f32 %0, %1;" : "=f"(y) : "f"(x)); return y;
}

__device__ __forceinline__ void mma_tf32(float& d0, float& d1, float& d2, float& d3,
                                         uint32_t a0, uint32_t a1, uint32_t a2, uint32_t a3,
                                         uint32_t b0, uint32_t b1) {
    asm volatile(
        "mma.sync.aligned.m16n8k8.row.col.f32.tf32.tf32.f32 "
        "{%0,%1,%2,%3}, {%4,%5,%6,%7}, {%8,%9}, {%0,%1,%2,%3};"
        : "+f"(d0), "+f"(d1), "+f"(d2), "+f"(d3)
        : "r"(a0), "r"(a1), "r"(a2), "r"(a3), "r"(b0), "r"(b1));
}

// ================= tf32 mma.sync GEMM: C[M,N] = A[M,K] @ W[N,K]^T + bias =================
#define KCH 16
#define NCHUNK (D_DIM / KCH)   // 72
#define SPAD 20

__global__ __launch_bounds__(256) void gemm_tf32_nt_bias(
    const float* __restrict__ A, const float* __restrict__ Bw,
    const float* __restrict__ bias, float* __restrict__ C)
{
    __shared__ float sA[2][128 * SPAD];
    __shared__ float sB[2][128 * SPAD];

    const int tid = threadIdx.x;
    const int wid = tid >> 5;
    const int lane = tid & 31;
    const int gid = lane >> 2;
    const int tig = lane & 3;
    const int wm = wid >> 2;
    const int wn = wid & 3;

    const int bm = blockIdx.y * 128;
    const int bn = blockIdx.x * 128;

    const int lrow = tid >> 1;
    const int lpart = (tid & 1) * 8;
    const float* Ag = A + (size_t)(bm + lrow) * D_DIM + lpart;
    const float* Bg = Bw + (size_t)(bn + lrow) * D_DIM + lpart;

    float4 pa0, pa1, pb0, pb1;

    auto prefetch = [&](int c) {
        const float* ag = Ag + c * KCH;
        const float* bg = Bg + c * KCH;
        pa0 = *(const float4*)(ag);
        pa1 = *(const float4*)(ag + 4);
        pb0 = *(const float4*)(bg);
        pb1 = *(const float4*)(bg + 4);
    };
    auto store_chunk = [&](int buf) {
        float4 v;
        v.x = to_tf32(pa0.x); v.y = to_tf32(pa0.y); v.z = to_tf32(pa0.z); v.w = to_tf32(pa0.w);
        *(float4*)(&sA[buf][lrow * SPAD + lpart]) = v;
        v.x = to_tf32(pa1.x); v.y = to_tf32(pa1.y); v.z = to_tf32(pa1.z); v.w = to_tf32(pa1.w);
        *(float4*)(&sA[buf][lrow * SPAD + lpart + 4]) = v;
        v.x = to_tf32(pb0.x); v.y = to_tf32(pb0.y); v.z = to_tf32(pb0.z); v.w = to_tf32(pb0.w);
        *(float4*)(&sB[buf][lrow * SPAD + lpart]) = v;
        v.x = to_tf32(pb1.x); v.y = to_tf32(pb1.y); v.z = to_tf32(pb1.z); v.w = to_tf32(pb1.w);
        *(float4*)(&sB[buf][lrow * SPAD + lpart + 4]) = v;
    };

    float acc[4][4][4];
#pragma unroll
    for (int i = 0; i < 4; i++)
#pragma unroll
        for (int j = 0; j < 4; j++)
#pragma unroll
            for (int r = 0; r < 4; r++) acc[i][j][r] = 0.f;

    prefetch(0);
    store_chunk(0);
    __syncthreads();

    for (int c = 0; c < NCHUNK; c++) {
        const int buf = c & 1;
        if (c + 1 < NCHUNK) prefetch(c + 1);

        const uint32_t* uA = (const uint32_t*)sA[buf];
        const uint32_t* uB = (const uint32_t*)sB[buf];

#pragma unroll
        for (int ks = 0; ks < 2; ks++) {
            const int k0 = ks * 8;
            uint32_t af[4][4], bf[4][2];
#pragma unroll
            for (int ma = 0; ma < 4; ma++) {
                int r0 = (wm * 64 + ma * 16 + gid) * SPAD;
                af[ma][0] = uA[r0 + k0 + tig];
                af[ma][1] = uA[r0 + 8 * SPAD + k0 + tig];
                af[ma][2] = uA[r0 + k0 + tig + 4];
                af[ma][3] = uA[r0 + 8 * SPAD + k0 + tig + 4];
            }
#pragma unroll
            for (int na = 0; na < 4; na++) {
                int r0 = (wn * 32 + na * 8 + gid) * SPAD;
                bf[na][0] = uB[r0 + k0 + tig];
                bf[na][1] = uB[r0 + k0 + tig + 4];
            }
#pragma unroll
            for (int ma = 0; ma < 4; ma++)
#pragma unroll
                for (int na = 0; na < 4; na++)
                    mma_tf32(acc[ma][na][0], acc[ma][na][1], acc[ma][na][2], acc[ma][na][3],
                             af[ma][0], af[ma][1], af[ma][2], af[ma][3],
                             bf[na][0], bf[na][1]);
        }

        if (c + 1 < NCHUNK) store_chunk(buf ^ 1);
        __syncthreads();
    }

#pragma unroll
    for (int ma = 0; ma < 4; ma++) {
        int row = bm + wm * 64 + ma * 16 + gid;
#pragma unroll
        for (int na = 0; na < 4; na++) {
            int col = bn + wn * 32 + na * 8 + tig * 2;
            float2 bb = *(const float2*)(bias + col);
            float2 o0, o1;
            o0.x = acc[ma][na][0] + bb.x;
            o0.y = acc[ma][na][1] + bb.y;
            o1.x = acc[ma][na][2] + bb.x;
            o1.y = acc[ma][na][3] + bb.y;
            *(float2*)(C + (size_t)row * D_DIM + col) = o0;
            *(float2*)(C + (size_t)(row + 8) * D_DIM + col) = o1;
        }
    }
}

// ---------------- RoPE (in-place on q and k) ----------------
__global__ void rope_kernel(float* __restrict__ q, float* __restrict__ k,
                            const float* __restrict__ cosp,
                            const float* __restrict__ sinp)
{
    int idx = blockIdx.x * blockDim.x + threadIdx.x;
    const int total = T_TOK * H_NUM * (DH / 2);
    if (idx >= total) return;
    int d = idx % (DH / 2);
    int th = idx / (DH / 2);
    int h = th % H_NUM;
    int t = th / H_NUM;

    float c = cosp[t * DH + d];
    float s = sinp[t * DH + d];
    size_t base = (size_t)t * D_DIM + h * DH;

    float q1 = q[base + d], q2 = q[base + d + DH / 2];
    q[base + d]          = q1 * c - q2 * s;
    q[base + d + DH / 2] = q2 * c + q1 * s;

    float k1 = k[base + d], k2 = k[base + d + DH / 2];
    k[base + d]          = k1 * c - k2 * s;
    k[base + d + DH / 2] = k2 * c + k1 * s;
}

// ---------------- Segment-masked flash attention (tf32 mma.sync) ----------------
// grid (T/64, H), 128 threads (4 warps x 16 query rows).
// smem strides: Q/K 76 (conflict-free A/B frag loads), V 72, P 68.
#define QT 64
#define KT 64
#define QK_STRIDE 76
#define V_STRIDE 72
#define P_STRIDE 68
#define ATTN_SMEM ((2 * QT * QK_STRIDE + KT * V_STRIDE + QT * P_STRIDE) * 4)

__global__ __launch_bounds__(128) void attn_kernel(
    const float* __restrict__ q, const float* __restrict__ k,
    const float* __restrict__ v, const int* __restrict__ cu,
    float* __restrict__ out)
{
    extern __shared__ float smemf[];
    float* sQ = smemf;                           // 64 x 76
    float* sK = sQ + QT * QK_STRIDE;             // 64 x 76
    float* sV = sK + QT * QK_STRIDE;             // 64 x 72
    float* sP = sV + KT * V_STRIDE;              // 64 x 68
    __shared__ int sCu[NCU];
    __shared__ int sSegQ[QT];
    __shared__ int sSegK[KT];

    const int tid = threadIdx.x;
    const int wid = tid >> 5;
    const int lane = tid & 31;
    const int gid = lane >> 2;
    const int tig = lane & 3;
    const int h = blockIdx.y;
    const int q0 = blockIdx.x * QT;

    if (tid < NCU) sCu[tid] = cu[tid];
    __syncthreads();

    // load Q tile (scaled + tf32-rounded); 64 rows x 18 float4
    const float scale = rsqrtf((float)DH);
    for (int i = tid; i < QT * (DH / 4); i += 128) {
        int r = i / (DH / 4), c4 = (i % (DH / 4)) * 4;
        float4 val = *(const float4*)(q + (size_t)(q0 + r) * D_DIM + h * DH + c4);
        val.x = to_tf32(val.x * scale); val.y = to_tf32(val.y * scale);
        val.z = to_tf32(val.z * scale); val.w = to_tf32(val.w * scale);
        *(float4*)(&sQ[r * QK_STRIDE + c4]) = val;
    }
    if (tid < QT) {
        int t = q0 + tid;
        int s = 0;
#pragma unroll
        for (int j = 1; j < NCU; j++)
            if (sCu[j] <= t) s = j;
        sSegQ[tid] = s;
    }
    __syncthreads();

    const int seg_lo = sSegQ[0];
    const int seg_hi = sSegQ[QT - 1];
    const int k_end = sCu[seg_hi + 1];
    const int kc0 = (sCu[seg_lo] / KT) * KT;

    const int r0 = wid * 16 + gid;       // local row of first accum row
    const int segq0 = sSegQ[r0];
    const int segq1 = sSegQ[r0 + 8];

    float m0 = -1e30f, m1 = -1e30f, l0 = 0.f, l1 = 0.f;
    float O[9][4];
#pragma unroll
    for (int no = 0; no < 9; no++)
#pragma unroll
        for (int r = 0; r < 4; r++) O[no][r] = 0.f;

    const uint32_t* uQ = (const uint32_t*)sQ;
    const uint32_t* uK = (const uint32_t*)sK;
    const uint32_t* uV = (const uint32_t*)sV;
    const uint32_t* uP = (const uint32_t*)sP;

    for (int kc = kc0; kc < k_end; kc += KT) {
        // load K/V tile (tf32-rounded) + segment ids for these keys
        for (int i = tid; i < KT * (DH / 4); i += 128) {
            int r = i / (DH / 4), c4 = (i % (DH / 4)) * 4;
            float4 kv = *(const float4*)(k + (size_t)(kc + r) * D_DIM + h * DH + c4);
            kv.x = to_tf32(kv.x); kv.y = to_tf32(kv.y);
            kv.z = to_tf32(kv.z); kv.w = to_tf32(kv.w);
            *(float4*)(&sK[r * QK_STRIDE + c4]) = kv;
            float4 vv = *(const float4*)(v + (size_t)(kc + r) * D_DIM + h * DH + c4);
            vv.x = to_tf32(vv.x); vv.y = to_tf32(vv.y);
            vv.z = to_tf32(vv.z); vv.w = to_tf32(vv.w);
            *(float4*)(&sV[r * V_STRIDE + c4]) = vv;
        }
        if (tid < KT) {
            int t = kc + tid;
            int s = 0;
#pragma unroll
            for (int j = 1; j < NCU; j++)
                if (sCu[j] <= t) s = j;
            sSegK[tid] = s;
        }
        __syncthreads();

        // ---- S = Q K^T : 8 n-atoms x 9 k-steps ----
        float accS[8][4];
#pragma unroll
        for (int na = 0; na < 8; na++)
#pragma unroll
            for (int r = 0; r < 4; r++) accS[na][r] = 0.f;

#pragma unroll
        for (int ks = 0; ks < 9; ks++) {
            const int k0 = ks * 8;
            uint32_t a0 = uQ[r0 * QK_STRIDE + k0 + tig];
            uint32_t a1 = uQ[(r0 + 8) * QK_STRIDE + k0 + tig];
            uint32_t a2 = uQ[r0 * QK_STRIDE + k0 + tig + 4];
            uint32_t a3 = uQ[(r0 + 8) * QK_STRIDE + k0 + tig + 4];
#pragma unroll
            for (int na = 0; na < 8; na++) {
                uint32_t b0 = uK[(na * 8 + gid) * QK_STRIDE + k0 + tig];
                uint32_t b1 = uK[(na * 8 + gid) * QK_STRIDE + k0 + tig + 4];
                mma_tf32(accS[na][0], accS[na][1], accS[na][2], accS[na][3],
                         a0, a1, a2, a3, b0, b1);
            }
        }

        // ---- mask ----
#pragma unroll
        for (int na = 0; na < 8; na++) {
            int c0 = na * 8 + tig * 2;
            int sk0 = sSegK[c0], sk1 = sSegK[c0 + 1];
            if (sk0 != segq0) accS[na][0] = -1e30f;
            if (sk1 != segq0) accS[na][1] = -1e30f;
            if (sk0 != segq1) accS[na][2] = -1e30f;
            if (sk1 != segq1) accS[na][3] = -1e30f;
        }

        // ---- online softmax ----
        float mt0 = -1e30f, mt1 = -1e30f;
#pragma unroll
        for (int na = 0; na < 8; na++) {
            mt0 = fmaxf(mt0, fmaxf(accS[na][0], accS[na][1]));
            mt1 = fmaxf(mt1, fmaxf(accS[na][2], accS[na][3]));
        }
        mt0 = fmaxf(mt0, __shfl_xor_sync(0xffffffffu, mt0, 1));
        mt0 = fmaxf(mt0, __shfl_xor_sync(0xffffffffu, mt0, 2));
        mt1 = fmaxf(mt1, __shfl_xor_sync(0xffffffffu, mt1, 1));
        mt1 = fmaxf(mt1, __shfl_xor_sync(0xffffffffu, mt1, 2));
        float mn0 = fmaxf(m0, mt0);
        float mn1 = fmaxf(m1, mt1);

        float ls0 = 0.f, ls1 = 0.f;
#pragma unroll
        for (int na = 0; na < 8; na++) {
            float p00 = (accS[na][0] < -1e29f) ? 0.f : to_tf32(__expf(accS[na][0] - mn0));
            float p01 = (accS[na][1] < -1e29f) ? 0.f : to_tf32(__expf(accS[na][1] - mn0));
            float p10 = (accS[na][2] < -1e29f) ? 0.f : to_tf32(__expf(accS[na][2] - mn1));
            float p11 = (accS[na][3] < -1e29f) ? 0.f : to_tf32(__expf(accS[na][3] - mn1));
            ls0 += p00 + p01;
            ls1 += p10 + p11;
            int c0 = na * 8 + tig * 2;
            *(float2*)(&sP[r0 * P_STRIDE + c0]) = make_float2(p00, p01);
            *(float2*)(&sP[(r0 + 8) * P_STRIDE + c0]) = make_float2(p10, p11);
        }
        ls0 += __shfl_xor_sync(0xffffffffu, ls0, 1);
        ls0 += __shfl_xor_sync(0xffffffffu, ls0, 2);
        ls1 += __shfl_xor_sync(0xffffffffu, ls1, 1);
        ls1 += __shfl_xor_sync(0xffffffffu, ls1, 2);

        float al0 = __expf(m0 - mn0);
        float al1 = __expf(m1 - mn1);
        l0 = l0 * al0 + ls0;
        l1 = l1 * al1 + ls1;
        m0 = mn0; m1 = mn1;

#pragma unroll
        for (int no = 0; no < 9; no++) {
            O[no][0] *= al0; O[no][1] *= al0;
            O[no][2] *= al1; O[no][3] *= al1;
        }
        __syncwarp();

        // ---- O += P V : 9 n-atoms x 8 k-steps ----
#pragma unroll
        for (int ks = 0; ks < 8; ks++) {
            const int k0 = ks * 8;
            uint32_t a0 = uP[r0 * P_STRIDE + k0 + tig];
            uint32_t a1 = uP[(r0 + 8) * P_STRIDE + k0 + tig];
            uint32_t a2 = uP[r0 * P_STRIDE + k0 + tig + 4];
            uint32_t a3 = uP[(r0 + 8) * P_STRIDE + k0 + tig + 4];
#pragma unroll
            for (int no = 0; no < 9; no++) {
                uint32_t b0 = uV[(k0 + tig) * V_STRIDE + no * 8 + gid];
                uint32_t b1 = uV[(k0 + tig + 4) * V_STRIDE + no * 8 + gid];
                mma_tf32(O[no][0], O[no][1], O[no][2], O[no][3],
                         a0, a1, a2, a3, b0, b1);
            }
        }
        __syncthreads();
    }

    float il0 = 1.f / l0;
    float il1 = 1.f / l1;
    size_t ob0 = (size_t)(q0 + r0) * D_DIM + h * DH;
    size_t ob1 = (size_t)(q0 + r0 + 8) * D_DIM + h * DH;
#pragma unroll
    for (int no = 0; no < 9; no++) {
        int c0 = no * 8 + tig * 2;
        *(float2*)(out + ob0 + c0) = make_float2(O[no][0] * il0, O[no][1] * il0);
        *(float2*)(out + ob1 + c0) = make_float2(O[no][2] * il1, O[no][3] * il1);
    }
}

// ---------------- host launch ----------------
extern "C" void kernel_launch(void* const* d_in, const int* in_sizes, int n_in,
                              void* d_out, int out_size)
{
    const float* hs   = (const float*)d_in[0];
    const int*   cu   = (const int*)  d_in[1];
    const float* cosp = (const float*)d_in[2];
    const float* sinp = (const float*)d_in[3];
    const float* Wq   = (const float*)d_in[4];
    const float* bq   = (const float*)d_in[5];
    const float* Wk   = (const float*)d_in[6];
    const float* bk   = (const float*)d_in[7];
    const float* Wv   = (const float*)d_in[8];
    const float* bv   = (const float*)d_in[9];
    const float* Wo   = (const float*)d_in[10];
    const float* bo   = (const float*)d_in[11];
    float* out = (float*)d_out;

    float *q, *k, *v, *attn;
    cudaGetSymbolAddress((void**)&q, g_q);
    cudaGetSymbolAddress((void**)&k, g_k);
    cudaGetSymbolAddress((void**)&v, g_v);
    cudaGetSymbolAddress((void**)&attn, g_attn);

    dim3 gemm_grid(D_DIM / 128, T_TOK / 128);  // (9, 16)
    gemm_tf32_nt_bias<<<gemm_grid, 256>>>(hs, Wq, bq, q);
    gemm_tf32_nt_bias<<<gemm_grid, 256>>>(hs, Wk, bk, k);
    gemm_tf32_nt_bias<<<gemm_grid, 256>>>(hs, Wv, bv, v);

    int rope_total = T_TOK * H_NUM * (DH / 2);
    rope_kernel<<<(rope_total + 255) / 256, 256>>>(q, k, cosp, sinp);

    cudaFuncSetAttribute(attn_kernel,
                         cudaFuncAttributeMaxDynamicSharedMemorySize, ATTN_SMEM);
    attn_kernel<<<dim3(T_TOK / QT, H_NUM), 128, ATTN_SMEM>>>(q, k, v, cu, attn);

    gemm_tf32_nt_bias<<<gemm_grid, 256>>>(attn, Wo, bo, out);
}

// round 7
// speedup vs baseline: 4.5760x; 1.0909x over previous
#include <cuda_runtime.h>
#include <cuda_bf16.h>
#include <cstdint>
#include <math.h>

#define T_TOK 2048
#define D_DIM 1152
#define H_NUM 16
#define DH 72
#define NCU 9

// ---------------- scratch (no allocations allowed) ----------------
__device__ float g_q[T_TOK * D_DIM];
__device__ float g_k[T_TOK * D_DIM];
__device__ float g_v[T_TOK * D_DIM];
__device__ float g_attn[T_TOK * D_DIM];
__device__ float g_hsr[T_TOK * D_DIM];          // tf32-rounded hidden_states
__device__ float g_wr[4][D_DIM * D_DIM];        // tf32-rounded Wq,Wk,Wv,Wo

__device__ __forceinline__ float to_tf32(float x) {
    float y; asm("cvt.rna.tf32.f32 %0, %1;" : "=f"(y) : "f"(x)); return y;
}

__device__ __forceinline__ uint32_t smem_u32(const void* p) {
    uint32_t a;
    asm("{ .reg .u64 t; cvta.to.shared.u64 t, %1; cvt.u32.u64 %0, t; }" : "=r"(a) : "l"(p));
    return a;
}
__device__ __forceinline__ void cp16(uint32_t s, const void* g) {
    asm volatile("cp.async.ca.shared.global [%0], [%1], 16;" :: "r"(s), "l"(g));
}
#define CP_COMMIT() asm volatile("cp.async.commit_group;" ::: "memory")
#define CP_WAIT(n)  asm volatile("cp.async.wait_group %0;" :: "n"(n) : "memory")

__device__ __forceinline__ void mma_tf32(float& d0, float& d1, float& d2, float& d3,
                                         uint32_t a0, uint32_t a1, uint32_t a2, uint32_t a3,
                                         uint32_t b0, uint32_t b1) {
    asm volatile(
        "mma.sync.aligned.m16n8k8.row.col.f32.tf32.tf32.f32 "
        "{%0,%1,%2,%3}, {%4,%5,%6,%7}, {%8,%9}, {%0,%1,%2,%3};"
        : "+f"(d0), "+f"(d1), "+f"(d2), "+f"(d3)
        : "r"(a0), "r"(a1), "r"(a2), "r"(a3), "r"(b0), "r"(b1));
}

// ---------------- pre-round pass: tf32-round hs + 4 weights ----------------
__global__ void round_tf32_kernel(const float* __restrict__ hs,
                                  const float* __restrict__ wq, const float* __restrict__ wk,
                                  const float* __restrict__ wv, const float* __restrict__ wo)
{
    const int seg = blockIdx.y;
    const float* src;
    float* dst;
    int n4;
    if (seg == 0) { src = hs; dst = g_hsr;   n4 = T_TOK * D_DIM / 4; }
    else {
        const float* ws[4] = {wq, wk, wv, wo};
        src = ws[seg - 1]; dst = g_wr[seg - 1]; n4 = D_DIM * D_DIM / 4;
    }
    int idx = blockIdx.x * blockDim.x + threadIdx.x;
    if (idx >= n4) return;
    float4 v = ((const float4*)src)[idx];
    v.x = to_tf32(v.x); v.y = to_tf32(v.y); v.z = to_tf32(v.z); v.w = to_tf32(v.w);
    ((float4*)dst)[idx] = v;
}

// ============ cp.async 4-stage tf32 GEMM: C = A @ W^T + bias ============
// Inputs pre-rounded to tf32. CTA 128x128, 8 warps (64x32), KCH=16.
#define KCH 16
#define NCHUNK (D_DIM / KCH)   // 72
#define SPAD 20
#define STAGES 4
#define STG_FLOATS (128 * SPAD)
#define GEMM_SMEM (STAGES * 2 * STG_FLOATS * 4)   // 81920 bytes

__global__ __launch_bounds__(256) void gemm_cp_tf32(
    const float* __restrict__ A,
    const float* __restrict__ W0, const float* __restrict__ W1, const float* __restrict__ W2,
    const float* __restrict__ b0, const float* __restrict__ b1, const float* __restrict__ b2,
    float* __restrict__ C0, float* __restrict__ C1, float* __restrict__ C2)
{
    extern __shared__ float smemf[];
    float* sA = smemf;                       // STAGES x 128 x SPAD
    float* sB = smemf + STAGES * STG_FLOATS;
    const uint32_t uAaddr = smem_u32(sA);
    const uint32_t uBaddr = smem_u32(sB);

    const int z = blockIdx.z;
    const float* Bw  = (z == 0) ? W0 : (z == 1) ? W1 : W2;
    const float* bia = (z == 0) ? b0 : (z == 1) ? b1 : b2;
    float* C         = (z == 0) ? C0 : (z == 1) ? C1 : C2;

    const int tid = threadIdx.x;
    const int wid = tid >> 5;
    const int lane = tid & 31;
    const int gid = lane >> 2;
    const int tig = lane & 3;
    const int wm = wid >> 2;
    const int wn = wid & 3;

    const int bm = blockIdx.y * 128;
    const int bn = blockIdx.x * 128;

    // cp.async loader: 512 float4 per matrix per stage; 2 each per thread
    auto issue = [&](int c, int stg) {
#pragma unroll
        for (int i = 0; i < 2; i++) {
            int idx = tid * 2 + i;
            int row = idx >> 2;
            int c4 = (idx & 3) * 4;
            uint32_t off = (uint32_t)(stg * STG_FLOATS + row * SPAD + c4) * 4u;
            cp16(uAaddr + off, A  + (size_t)(bm + row) * D_DIM + c * KCH + c4);
            cp16(uBaddr + off, Bw + (size_t)(bn + row) * D_DIM + c * KCH + c4);
        }
    };

    float acc[4][4][4];
#pragma unroll
    for (int i = 0; i < 4; i++)
#pragma unroll
        for (int j = 0; j < 4; j++)
#pragma unroll
            for (int r = 0; r < 4; r++) acc[i][j][r] = 0.f;

    // prologue: stages 0..2
#pragma unroll
    for (int c = 0; c < STAGES - 1; c++) {
        issue(c, c);
        CP_COMMIT();
    }

    for (int c = 0; c < NCHUNK; c++) {
        CP_WAIT(STAGES - 2);
        __syncthreads();

        const int stg = c & (STAGES - 1);
        const uint32_t* uA = (const uint32_t*)(sA + stg * STG_FLOATS);
        const uint32_t* uB = (const uint32_t*)(sB + stg * STG_FLOATS);

#pragma unroll
        for (int ks = 0; ks < 2; ks++) {
            const int k0 = ks * 8;
            uint32_t af[4][4], bf[4][2];
#pragma unroll
            for (int ma = 0; ma < 4; ma++) {
                int r0 = (wm * 64 + ma * 16 + gid) * SPAD;
                af[ma][0] = uA[r0 + k0 + tig];
                af[ma][1] = uA[r0 + 8 * SPAD + k0 + tig];
                af[ma][2] = uA[r0 + k0 + tig + 4];
                af[ma][3] = uA[r0 + 8 * SPAD + k0 + tig + 4];
            }
#pragma unroll
            for (int na = 0; na < 4; na++) {
                int r0 = (wn * 32 + na * 8 + gid) * SPAD;
                bf[na][0] = uB[r0 + k0 + tig];
                bf[na][1] = uB[r0 + k0 + tig + 4];
            }
#pragma unroll
            for (int ma = 0; ma < 4; ma++)
#pragma unroll
                for (int na = 0; na < 4; na++)
                    mma_tf32(acc[ma][na][0], acc[ma][na][1], acc[ma][na][2], acc[ma][na][3],
                             af[ma][0], af[ma][1], af[ma][2], af[ma][3],
                             bf[na][0], bf[na][1]);
        }

        if (c + STAGES - 1 < NCHUNK)
            issue(c + STAGES - 1, (c + STAGES - 1) & (STAGES - 1));
        CP_COMMIT();   // unconditional: keeps wait_group accounting uniform
    }

#pragma unroll
    for (int ma = 0; ma < 4; ma++) {
        int row = bm + wm * 64 + ma * 16 + gid;
#pragma unroll
        for (int na = 0; na < 4; na++) {
            int col = bn + wn * 32 + na * 8 + tig * 2;
            float2 bb = *(const float2*)(bia + col);
            float2 o0, o1;
            o0.x = acc[ma][na][0] + bb.x;
            o0.y = acc[ma][na][1] + bb.y;
            o1.x = acc[ma][na][2] + bb.x;
            o1.y = acc[ma][na][3] + bb.y;
            *(float2*)(C + (size_t)row * D_DIM + col) = o0;
            *(float2*)(C + (size_t)(row + 8) * D_DIM + col) = o1;
        }
    }
}

// ---------------- RoPE (in-place on q and k) ----------------
__global__ void rope_kernel(float* __restrict__ q, float* __restrict__ k,
                            const float* __restrict__ cosp,
                            const float* __restrict__ sinp)
{
    int idx = blockIdx.x * blockDim.x + threadIdx.x;
    const int total = T_TOK * H_NUM * (DH / 2);
    if (idx >= total) return;
    int d = idx % (DH / 2);
    int th = idx / (DH / 2);
    int h = th % H_NUM;
    int t = th / H_NUM;

    float c = cosp[t * DH + d];
    float s = sinp[t * DH + d];
    size_t base = (size_t)t * D_DIM + h * DH;

    float q1 = q[base + d], q2 = q[base + d + DH / 2];
    q[base + d]          = q1 * c - q2 * s;
    q[base + d + DH / 2] = q2 * c + q1 * s;

    float k1 = k[base + d], k2 = k[base + d + DH / 2];
    k[base + d]          = k1 * c - k2 * s;
    k[base + d + DH / 2] = k2 * c + k1 * s;
}

// ---------------- Segment-masked flash attention (tf32 mma.sync) ----------------
#define QT 64
#define KT 64
#define QK_STRIDE 76
#define V_STRIDE 72
#define P_STRIDE 68
#define ATTN_SMEM ((2 * QT * QK_STRIDE + KT * V_STRIDE + QT * P_STRIDE) * 4)

__global__ __launch_bounds__(128) void attn_kernel(
    const float* __restrict__ q, const float* __restrict__ k,
    const float* __restrict__ v, const int* __restrict__ cu,
    float* __restrict__ out)
{
    extern __shared__ float smemf[];
    float* sQ = smemf;
    float* sK = sQ + QT * QK_STRIDE;
    float* sV = sK + QT * QK_STRIDE;
    float* sP = sV + KT * V_STRIDE;
    __shared__ int sCu[NCU];
    __shared__ int sSegQ[QT];
    __shared__ int sSegK[KT];

    const int tid = threadIdx.x;
    const int wid = tid >> 5;
    const int lane = tid & 31;
    const int gid = lane >> 2;
    const int tig = lane & 3;
    const int h = blockIdx.y;
    const int q0 = blockIdx.x * QT;

    if (tid < NCU) sCu[tid] = cu[tid];
    __syncthreads();

    const float scale = rsqrtf((float)DH);
    for (int i = tid; i < QT * (DH / 4); i += 128) {
        int r = i / (DH / 4), c4 = (i % (DH / 4)) * 4;
        float4 val = *(const float4*)(q + (size_t)(q0 + r) * D_DIM + h * DH + c4);
        val.x = to_tf32(val.x * scale); val.y = to_tf32(val.y * scale);
        val.z = to_tf32(val.z * scale); val.w = to_tf32(val.w * scale);
        *(float4*)(&sQ[r * QK_STRIDE + c4]) = val;
    }
    if (tid < QT) {
        int t = q0 + tid;
        int s = 0;
#pragma unroll
        for (int j = 1; j < NCU; j++)
            if (sCu[j] <= t) s = j;
        sSegQ[tid] = s;
    }
    __syncthreads();

    const int seg_lo = sSegQ[0];
    const int seg_hi = sSegQ[QT - 1];
    const int k_end = sCu[seg_hi + 1];
    const int kc0 = (sCu[seg_lo] / KT) * KT;

    const int r0 = wid * 16 + gid;
    const int segq0 = sSegQ[r0];
    const int segq1 = sSegQ[r0 + 8];

    float m0 = -1e30f, m1 = -1e30f, l0 = 0.f, l1 = 0.f;
    float O[9][4];
#pragma unroll
    for (int no = 0; no < 9; no++)
#pragma unroll
        for (int r = 0; r < 4; r++) O[no][r] = 0.f;

    const uint32_t* uQ = (const uint32_t*)sQ;
    const uint32_t* uK = (const uint32_t*)sK;
    const uint32_t* uV = (const uint32_t*)sV;
    const uint32_t* uP = (const uint32_t*)sP;

    for (int kc = kc0; kc < k_end; kc += KT) {
        for (int i = tid; i < KT * (DH / 4); i += 128) {
            int r = i / (DH / 4), c4 = (i % (DH / 4)) * 4;
            float4 kv = *(const float4*)(k + (size_t)(kc + r) * D_DIM + h * DH + c4);
            kv.x = to_tf32(kv.x); kv.y = to_tf32(kv.y);
            kv.z = to_tf32(kv.z); kv.w = to_tf32(kv.w);
            *(float4*)(&sK[r * QK_STRIDE + c4]) = kv;
            float4 vv = *(const float4*)(v + (size_t)(kc + r) * D_DIM + h * DH + c4);
            vv.x = to_tf32(vv.x); vv.y = to_tf32(vv.y);
            vv.z = to_tf32(vv.z); vv.w = to_tf32(vv.w);
            *(float4*)(&sV[r * V_STRIDE + c4]) = vv;
        }
        if (tid < KT) {
            int t = kc + tid;
            int s = 0;
#pragma unroll
            for (int j = 1; j < NCU; j++)
                if (sCu[j] <= t) s = j;
            sSegK[tid] = s;
        }
        __syncthreads();

        float accS[8][4];
#pragma unroll
        for (int na = 0; na < 8; na++)
#pragma unroll
            for (int r = 0; r < 4; r++) accS[na][r] = 0.f;

#pragma unroll
        for (int ks = 0; ks < 9; ks++) {
            const int k0 = ks * 8;
            uint32_t a0 = uQ[r0 * QK_STRIDE + k0 + tig];
            uint32_t a1 = uQ[(r0 + 8) * QK_STRIDE + k0 + tig];
            uint32_t a2 = uQ[r0 * QK_STRIDE + k0 + tig + 4];
            uint32_t a3 = uQ[(r0 + 8) * QK_STRIDE + k0 + tig + 4];
#pragma unroll
            for (int na = 0; na < 8; na++) {
                uint32_t b0 = uK[(na * 8 + gid) * QK_STRIDE + k0 + tig];
                uint32_t b1 = uK[(na * 8 + gid) * QK_STRIDE + k0 + tig + 4];
                mma_tf32(accS[na][0], accS[na][1], accS[na][2], accS[na][3],
                         a0, a1, a2, a3, b0, b1);
            }
        }

#pragma unroll
        for (int na = 0; na < 8; na++) {
            int c0 = na * 8 + tig * 2;
            int sk0 = sSegK[c0], sk1 = sSegK[c0 + 1];
            if (sk0 != segq0) accS[na][0] = -1e30f;
            if (sk1 != segq0) accS[na][1] = -1e30f;
            if (sk0 != segq1) accS[na][2] = -1e30f;
            if (sk1 != segq1) accS[na][3] = -1e30f;
        }

        float mt0 = -1e30f, mt1 = -1e30f;
#pragma unroll
        for (int na = 0; na < 8; na++) {
            mt0 = fmaxf(mt0, fmaxf(accS[na][0], accS[na][1]));
            mt1 = fmaxf(mt1, fmaxf(accS[na][2], accS[na][3]));
        }
        mt0 = fmaxf(mt0, __shfl_xor_sync(0xffffffffu, mt0, 1));
        mt0 = fmaxf(mt0, __shfl_xor_sync(0xffffffffu, mt0, 2));
        mt1 = fmaxf(mt1, __shfl_xor_sync(0xffffffffu, mt1, 1));
        mt1 = fmaxf(mt1, __shfl_xor_sync(0xffffffffu, mt1, 2));
        float mn0 = fmaxf(m0, mt0);
        float mn1 = fmaxf(m1, mt1);

        float ls0 = 0.f, ls1 = 0.f;
#pragma unroll
        for (int na = 0; na < 8; na++) {
            float p00 = (accS[na][0] < -1e29f) ? 0.f : to_tf32(__expf(accS[na][0] - mn0));
            float p01 = (accS[na][1] < -1e29f) ? 0.f : to_tf32(__expf(accS[na][1] - mn0));
            float p10 = (accS[na][2] < -1e29f) ? 0.f : to_tf32(__expf(accS[na][2] - mn1));
            float p11 = (accS[na][3] < -1e29f) ? 0.f : to_tf32(__expf(accS[na][3] - mn1));
            ls0 += p00 + p01;
            ls1 += p10 + p11;
            int c0 = na * 8 + tig * 2;
            *(float2*)(&sP[r0 * P_STRIDE + c0]) = make_float2(p00, p01);
            *(float2*)(&sP[(r0 + 8) * P_STRIDE + c0]) = make_float2(p10, p11);
        }
        ls0 += __shfl_xor_sync(0xffffffffu, ls0, 1);
        ls0 += __shfl_xor_sync(0xffffffffu, ls0, 2);
        ls1 += __shfl_xor_sync(0xffffffffu, ls1, 1);
        ls1 += __shfl_xor_sync(0xffffffffu, ls1, 2);

        float al0 = __expf(m0 - mn0);
        float al1 = __expf(m1 - mn1);
        l0 = l0 * al0 + ls0;
        l1 = l1 * al1 + ls1;
        m0 = mn0; m1 = mn1;

#pragma unroll
        for (int no = 0; no < 9; no++) {
            O[no][0] *= al0; O[no][1] *= al0;
            O[no][2] *= al1; O[no][3] *= al1;
        }
        __syncwarp();

#pragma unroll
        for (int ks = 0; ks < 8; ks++) {
            const int k0 = ks * 8;
            uint32_t a0 = uP[r0 * P_STRIDE + k0 + tig];
            uint32_t a1 = uP[(r0 + 8) * P_STRIDE + k0 + tig];
            uint32_t a2 = uP[r0 * P_STRIDE + k0 + tig + 4];
            uint32_t a3 = uP[(r0 + 8) * P_STRIDE + k0 + tig + 4];
#pragma unroll
            for (int no = 0; no < 9; no++) {
                uint32_t b0 = uV[(k0 + tig) * V_STRIDE + no * 8 + gid];
                uint32_t b1 = uV[(k0 + tig + 4) * V_STRIDE + no * 8 + gid];
                mma_tf32(O[no][0], O[no][1], O[no][2], O[no][3],
                         a0, a1, a2, a3, b0, b1);
            }
        }
        __syncthreads();
    }

    // store tf32-rounded so the O-projection GEMM can consume directly
    float il0 = 1.f / l0;
    float il1 = 1.f / l1;
    size_t ob0 = (size_t)(q0 + r0) * D_DIM + h * DH;
    size_t ob1 = (size_t)(q0 + r0 + 8) * D_DIM + h * DH;
#pragma unroll
    for (int no = 0; no < 9; no++) {
        int c0 = no * 8 + tig * 2;
        *(float2*)(out + ob0 + c0) = make_float2(to_tf32(O[no][0] * il0), to_tf32(O[no][1] * il0));
        *(float2*)(out + ob1 + c0) = make_float2(to_tf32(O[no][2] * il1), to_tf32(O[no][3] * il1));
    }
}

// ---------------- host launch ----------------
extern "C" void kernel_launch(void* const* d_in, const int* in_sizes, int n_in,
                              void* d_out, int out_size)
{
    const float* hs   = (const float*)d_in[0];
    const int*   cu   = (const int*)  d_in[1];
    const float* cosp = (const float*)d_in[2];
    const float* sinp = (const float*)d_in[3];
    const float* Wq   = (const float*)d_in[4];
    const float* bq   = (const float*)d_in[5];
    const float* Wk   = (const float*)d_in[6];
    const float* bk   = (const float*)d_in[7];
    const float* Wv   = (const float*)d_in[8];
    const float* bv   = (const float*)d_in[9];
    const float* Wo   = (const float*)d_in[10];
    const float* bo   = (const float*)d_in[11];
    float* out = (float*)d_out;

    float *q, *k, *v, *attn, *hsr, *wr;
    cudaGetSymbolAddress((void**)&q, g_q);
    cudaGetSymbolAddress((void**)&k, g_k);
    cudaGetSymbolAddress((void**)&v, g_v);
    cudaGetSymbolAddress((void**)&attn, g_attn);
    cudaGetSymbolAddress((void**)&hsr, g_hsr);
    cudaGetSymbolAddress((void**)&wr, g_wr);
    float* wqr = wr;
    float* wkr = wr + (size_t)D_DIM * D_DIM;
    float* wvr = wr + 2 * (size_t)D_DIM * D_DIM;
    float* wor = wr + 3 * (size_t)D_DIM * D_DIM;

    // pre-round hs + weights (seg y=0..4)
    // FIX(R7): grid x must cover the LARGEST segment (hs: T_TOK*D_DIM/4),
    // not the weight size — R6 left 44% of g_hsr uninitialized.
    int n4hs = T_TOK * D_DIM / 4;
    dim3 rgrid((n4hs + 255) / 256, 5);
    round_tf32_kernel<<<rgrid, 256>>>(hs, Wq, Wk, Wv, Wo);

    cudaFuncSetAttribute(gemm_cp_tf32,
                         cudaFuncAttributeMaxDynamicSharedMemorySize, GEMM_SMEM);

    // fused QKV
    dim3 qkv_grid(D_DIM / 128, T_TOK / 128, 3);
    gemm_cp_tf32<<<qkv_grid, 256, GEMM_SMEM>>>(hsr, wqr, wkr, wvr, bq, bk, bv, q, k, v);

    int rope_total = T_TOK * H_NUM * (DH / 2);
    rope_kernel<<<(rope_total + 255) / 256, 256>>>(q, k, cosp, sinp);

    cudaFuncSetAttribute(attn_kernel,
                         cudaFuncAttributeMaxDynamicSharedMemorySize, ATTN_SMEM);
    attn_kernel<<<dim3(T_TOK / QT, H_NUM), 128, ATTN_SMEM>>>(q, k, v, cu, attn);

    // O projection (z=1 grid, same pointers in all slots)
    dim3 o_grid(D_DIM / 128, T_TOK / 128, 1);
    gemm_cp_tf32<<<o_grid, 256, GEMM_SMEM>>>(attn, wor, wor, wor, bo, bo, bo, out, out, out);
}

// round 10
// speedup vs baseline: 4.5811x; 1.0011x over previous
#include <cuda_runtime.h>
#include <cuda_bf16.h>
#include <cstdint>
#include <math.h>

#define T_TOK 2048
#define D_DIM 1152
#define H_NUM 16
#define DH 72
#define NCU 9

// ---------------- scratch (no allocations allowed) ----------------
__device__ float g_q[T_TOK * D_DIM];
__device__ float g_k[T_TOK * D_DIM];
__device__ float g_v[T_TOK * D_DIM];
__device__ float g_attn[T_TOK * D_DIM];
__device__ float g_hsr[T_TOK * D_DIM];          // tf32-rounded hidden_states
__device__ float g_wr[4][D_DIM * D_DIM];        // tf32-rounded Wq,Wk,Wv,Wo

__device__ __forceinline__ float to_tf32(float x) {
    float y; asm("cvt.rna.tf32.f32 %0, %1;" : "=f"(y) : "f"(x)); return y;
}

__device__ __forceinline__ uint32_t smem_u32(const void* p) {
    uint32_t a;
    asm("{ .reg .u64 t; cvta.to.shared.u64 t, %1; cvt.u32.u64 %0, t; }" : "=r"(a) : "l"(p));
    return a;
}
__device__ __forceinline__ void cp16(uint32_t s, const void* g) {
    asm volatile("cp.async.ca.shared.global [%0], [%1], 16;" :: "r"(s), "l"(g));
}
#define CP_COMMIT() asm volatile("cp.async.commit_group;" ::: "memory")
#define CP_WAIT(n)  asm volatile("cp.async.wait_group %0;" :: "n"(n) : "memory")

__device__ __forceinline__ void mma_tf32(float& d0, float& d1, float& d2, float& d3,
                                         uint32_t a0, uint32_t a1, uint32_t a2, uint32_t a3,
                                         uint32_t b0, uint32_t b1) {
    asm volatile(
        "mma.sync.aligned.m16n8k8.row.col.f32.tf32.tf32.f32 "
        "{%0,%1,%2,%3}, {%4,%5,%6,%7}, {%8,%9}, {%0,%1,%2,%3};"
        : "+f"(d0), "+f"(d1), "+f"(d2), "+f"(d3)
        : "r"(a0), "r"(a1), "r"(a2), "r"(a3), "r"(b0), "r"(b1));
}

// ---------------- pre-round pass: tf32-round hs + 4 weights ----------------
__global__ void round_tf32_kernel(const float* __restrict__ hs,
                                  const float* __restrict__ wq, const float* __restrict__ wk,
                                  const float* __restrict__ wv, const float* __restrict__ wo)
{
    const int seg = blockIdx.y;
    const float* src;
    float* dst;
    int n4;
    if (seg == 0) { src = hs; dst = g_hsr;   n4 = T_TOK * D_DIM / 4; }
    else {
        const float* ws[4] = {wq, wk, wv, wo};
        src = ws[seg - 1]; dst = g_wr[seg - 1]; n4 = D_DIM * D_DIM / 4;
    }
    int idx = blockIdx.x * blockDim.x + threadIdx.x;
    if (idx >= n4) return;
    float4 v = ((const float4*)src)[idx];
    v.x = to_tf32(v.x); v.y = to_tf32(v.y); v.z = to_tf32(v.z); v.w = to_tf32(v.w);
    ((float4*)dst)[idx] = v;
}

// ============ cp.async 4-stage tf32 GEMM: C = A @ W^T + bias ============
#define KCH 16
#define NCHUNK (D_DIM / KCH)   // 72
#define SPAD 20
#define STAGES 4
#define STG_FLOATS (128 * SPAD)
#define GEMM_SMEM (STAGES * 2 * STG_FLOATS * 4)   // 81920 bytes

__global__ __launch_bounds__(256) void gemm_cp_tf32(
    const float* __restrict__ A,
    const float* __restrict__ W0, const float* __restrict__ W1, const float* __restrict__ W2,
    const float* __restrict__ b0, const float* __restrict__ b1, const float* __restrict__ b2,
    float* __restrict__ C0, float* __restrict__ C1, float* __restrict__ C2)
{
    extern __shared__ float smemf[];
    float* sA = smemf;
    float* sB = smemf + STAGES * STG_FLOATS;
    const uint32_t uAaddr = smem_u32(sA);
    const uint32_t uBaddr = smem_u32(sB);

    const int z = blockIdx.z;
    const float* Bw  = (z == 0) ? W0 : (z == 1) ? W1 : W2;
    const float* bia = (z == 0) ? b0 : (z == 1) ? b1 : b2;
    float* C         = (z == 0) ? C0 : (z == 1) ? C1 : C2;

    const int tid = threadIdx.x;
    const int wid = tid >> 5;
    const int lane = tid & 31;
    const int gid = lane >> 2;
    const int tig = lane & 3;
    const int wm = wid >> 2;
    const int wn = wid & 3;

    const int bm = blockIdx.y * 128;
    const int bn = blockIdx.x * 128;

    auto issue = [&](int c, int stg) {
#pragma unroll
        for (int i = 0; i < 2; i++) {
            int idx = tid * 2 + i;
            int row = idx >> 2;
            int c4 = (idx & 3) * 4;
            uint32_t off = (uint32_t)(stg * STG_FLOATS + row * SPAD + c4) * 4u;
            cp16(uAaddr + off, A  + (size_t)(bm + row) * D_DIM + c * KCH + c4);
            cp16(uBaddr + off, Bw + (size_t)(bn + row) * D_DIM + c * KCH + c4);
        }
    };

    float acc[4][4][4];
#pragma unroll
    for (int i = 0; i < 4; i++)
#pragma unroll
        for (int j = 0; j < 4; j++)
#pragma unroll
            for (int r = 0; r < 4; r++) acc[i][j][r] = 0.f;

#pragma unroll
    for (int c = 0; c < STAGES - 1; c++) {
        issue(c, c);
        CP_COMMIT();
    }

    for (int c = 0; c < NCHUNK; c++) {
        CP_WAIT(STAGES - 2);
        __syncthreads();

        const int stg = c & (STAGES - 1);
        const uint32_t* uA = (const uint32_t*)(sA + stg * STG_FLOATS);
        const uint32_t* uB = (const uint32_t*)(sB + stg * STG_FLOATS);

#pragma unroll
        for (int ks = 0; ks < 2; ks++) {
            const int k0 = ks * 8;
            uint32_t af[4][4], bf[4][2];
#pragma unroll
            for (int ma = 0; ma < 4; ma++) {
                int r0 = (wm * 64 + ma * 16 + gid) * SPAD;
                af[ma][0] = uA[r0 + k0 + tig];
                af[ma][1] = uA[r0 + 8 * SPAD + k0 + tig];
                af[ma][2] = uA[r0 + k0 + tig + 4];
                af[ma][3] = uA[r0 + 8 * SPAD + k0 + tig + 4];
            }
#pragma unroll
            for (int na = 0; na < 4; na++) {
                int r0 = (wn * 32 + na * 8 + gid) * SPAD;
                bf[na][0] = uB[r0 + k0 + tig];
                bf[na][1] = uB[r0 + k0 + tig + 4];
            }
#pragma unroll
            for (int ma = 0; ma < 4; ma++)
#pragma unroll
                for (int na = 0; na < 4; na++)
                    mma_tf32(acc[ma][na][0], acc[ma][na][1], acc[ma][na][2], acc[ma][na][3],
                             af[ma][0], af[ma][1], af[ma][2], af[ma][3],
                             bf[na][0], bf[na][1]);
        }

        if (c + STAGES - 1 < NCHUNK)
            issue(c + STAGES - 1, (c + STAGES - 1) & (STAGES - 1));
        CP_COMMIT();
    }

#pragma unroll
    for (int ma = 0; ma < 4; ma++) {
        int row = bm + wm * 64 + ma * 16 + gid;
#pragma unroll
        for (int na = 0; na < 4; na++) {
            int col = bn + wn * 32 + na * 8 + tig * 2;
            float2 bb = *(const float2*)(bia + col);
            float2 o0, o1;
            o0.x = acc[ma][na][0] + bb.x;
            o0.y = acc[ma][na][1] + bb.y;
            o1.x = acc[ma][na][2] + bb.x;
            o1.y = acc[ma][na][3] + bb.y;
            *(float2*)(C + (size_t)row * D_DIM + col) = o0;
            *(float2*)(C + (size_t)(row + 8) * D_DIM + col) = o1;
        }
    }
}

// ---------------- Segment-masked flash attention (tf32 mma.sync, fused RoPE) ----------------
// grid (T/128, H), 256 threads (8 warps x 16 query rows). K-tile 64.
#define QT 128
#define KT 64
#define QK_STRIDE 76
#define V_STRIDE 72
#define P_STRIDE 68
#define ATTN_SMEM ((QT * QK_STRIDE + KT * QK_STRIDE + KT * V_STRIDE + QT * P_STRIDE) * 4)

__global__ __launch_bounds__(256) void attn_kernel(
    const float* __restrict__ q, const float* __restrict__ k,
    const float* __restrict__ v, const int* __restrict__ cu,
    const float* __restrict__ cosp, const float* __restrict__ sinp,
    float* __restrict__ out)
{
    extern __shared__ float smemf[];
    float* sQ = smemf;                            // 128 x 76
    float* sK = sQ + QT * QK_STRIDE;              // 64 x 76
    float* sV = sK + KT * QK_STRIDE;              // 64 x 72
    float* sP = sV + KT * V_STRIDE;               // 128 x 68
    __shared__ int sCu[NCU];
    __shared__ int sSegQ[QT];
    __shared__ int sSegK[KT];

    const int tid = threadIdx.x;
    const int wid = tid >> 5;
    const int lane = tid & 31;
    const int gid = lane >> 2;
    const int tig = lane & 3;
    const int h = blockIdx.y;
    const int q0 = blockIdx.x * QT;

    if (tid < NCU) sCu[tid] = cu[tid];
    __syncthreads();

    const float scale = rsqrtf((float)DH);

    // ---- load Q with fused RoPE: pairs (d, d+36), d in [0,36) (9 float4 pairs/row) ----
    for (int i = tid; i < QT * 9; i += 256) {
        int r = i / 9, c4 = (i % 9) * 4;
        int t = q0 + r;
        const float* qrow = q + (size_t)t * D_DIM + h * DH;
        float4 x1 = *(const float4*)(qrow + c4);
        float4 x2 = *(const float4*)(qrow + c4 + 36);
        float4 cc = *(const float4*)(cosp + (size_t)t * DH + c4);
        float4 ss = *(const float4*)(sinp + (size_t)t * DH + c4);
        float4 o1, o2;
        o1.x = to_tf32((x1.x * cc.x - x2.x * ss.x) * scale);
        o1.y = to_tf32((x1.y * cc.y - x2.y * ss.y) * scale);
        o1.z = to_tf32((x1.z * cc.z - x2.z * ss.z) * scale);
        o1.w = to_tf32((x1.w * cc.w - x2.w * ss.w) * scale);
        o2.x = to_tf32((x2.x * cc.x + x1.x * ss.x) * scale);
        o2.y = to_tf32((x2.y * cc.y + x1.y * ss.y) * scale);
        o2.z = to_tf32((x2.z * cc.z + x1.z * ss.z) * scale);
        o2.w = to_tf32((x2.w * cc.w + x1.w * ss.w) * scale);
        *(float4*)(&sQ[r * QK_STRIDE + c4]) = o1;
        *(float4*)(&sQ[r * QK_STRIDE + c4 + 36]) = o2;
    }
    if (tid < QT) {
        int t = q0 + tid;
        int s = 0;
#pragma unroll
        for (int j = 1; j < NCU; j++)
            if (sCu[j] <= t) s = j;
        sSegQ[tid] = s;
    }
    __syncthreads();

    const int seg_lo = sSegQ[0];
    const int seg_hi = sSegQ[QT - 1];
    const int k_end = sCu[seg_hi + 1];
    const int kc0 = (sCu[seg_lo] / KT) * KT;

    const int r0 = wid * 16 + gid;            // first accum row (second is r0+8)
    const int segq0 = sSegQ[r0];
    const int segq1 = sSegQ[r0 + 8];

    float m0 = -1e30f, m1 = -1e30f, l0 = 0.f, l1 = 0.f;
    float O[9][4];
#pragma unroll
    for (int no = 0; no < 9; no++)
#pragma unroll
        for (int r = 0; r < 4; r++) O[no][r] = 0.f;

    const uint32_t* uQ = (const uint32_t*)sQ;
    const uint32_t* uK = (const uint32_t*)sK;
    const uint32_t* uV = (const uint32_t*)sV;
    const uint32_t* uP = (const uint32_t*)sP;

    for (int kc = kc0; kc < k_end; kc += KT) {
        // ---- load K with fused RoPE ----
        for (int i = tid; i < KT * 9; i += 256) {
            int r = i / 9, c4 = (i % 9) * 4;
            int t = kc + r;
            const float* krow = k + (size_t)t * D_DIM + h * DH;
            float4 x1 = *(const float4*)(krow + c4);
            float4 x2 = *(const float4*)(krow + c4 + 36);
            float4 cc = *(const float4*)(cosp + (size_t)t * DH + c4);
            float4 ss = *(const float4*)(sinp + (size_t)t * DH + c4);
            float4 o1, o2;
            o1.x = to_tf32(x1.x * cc.x - x2.x * ss.x);
            o1.y = to_tf32(x1.y * cc.y - x2.y * ss.y);
            o1.z = to_tf32(x1.z * cc.z - x2.z * ss.z);
            o1.w = to_tf32(x1.w * cc.w - x2.w * ss.w);
            o2.x = to_tf32(x2.x * cc.x + x1.x * ss.x);
            o2.y = to_tf32(x2.y * cc.y + x1.y * ss.y);
            o2.z = to_tf32(x2.z * cc.z + x1.z * ss.z);
            o2.w = to_tf32(x2.w * cc.w + x1.w * ss.w);
            *(float4*)(&sK[r * QK_STRIDE + c4]) = o1;
            *(float4*)(&sK[r * QK_STRIDE + c4 + 36]) = o2;
        }
        // ---- load V ----
        for (int i = tid; i < KT * (DH / 4); i += 256) {
            int r = i / (DH / 4), c4 = (i % (DH / 4)) * 4;
            float4 vv = *(const float4*)(v + (size_t)(kc + r) * D_DIM + h * DH + c4);
            vv.x = to_tf32(vv.x); vv.y = to_tf32(vv.y);
            vv.z = to_tf32(vv.z); vv.w = to_tf32(vv.w);
            *(float4*)(&sV[r * V_STRIDE + c4]) = vv;
        }
        if (tid < KT) {
            int t = kc + tid;
            int s = 0;
#pragma unroll
            for (int j = 1; j < NCU; j++)
                if (sCu[j] <= t) s = j;
            sSegK[tid] = s;
        }
        __syncthreads();

        // ---- S = Q K^T ----
        float accS[8][4];
#pragma unroll
        for (int na = 0; na < 8; na++)
#pragma unroll
            for (int r = 0; r < 4; r++) accS[na][r] = 0.f;

#pragma unroll
        for (int ks = 0; ks < 9; ks++) {
            const int k0 = ks * 8;
            uint32_t a0 = uQ[r0 * QK_STRIDE + k0 + tig];
            uint32_t a1 = uQ[(r0 + 8) * QK_STRIDE + k0 + tig];
            uint32_t a2 = uQ[r0 * QK_STRIDE + k0 + tig + 4];
            uint32_t a3 = uQ[(r0 + 8) * QK_STRIDE + k0 + tig + 4];
#pragma unroll
            for (int na = 0; na < 8; na++) {
                uint32_t b0 = uK[(na * 8 + gid) * QK_STRIDE + k0 + tig];
                uint32_t b1 = uK[(na * 8 + gid) * QK_STRIDE + k0 + tig + 4];
                mma_tf32(accS[na][0], accS[na][1], accS[na][2], accS[na][3],
                         a0, a1, a2, a3, b0, b1);
            }
        }

        // ---- mask ----
#pragma unroll
        for (int na = 0; na < 8; na++) {
            int c0 = na * 8 + tig * 2;
            int sk0 = sSegK[c0], sk1 = sSegK[c0 + 1];
            if (sk0 != segq0) accS[na][0] = -1e30f;
            if (sk1 != segq0) accS[na][1] = -1e30f;
            if (sk0 != segq1) accS[na][2] = -1e30f;
            if (sk1 != segq1) accS[na][3] = -1e30f;
        }

        // ---- online softmax ----
        float mt0 = -1e30f, mt1 = -1e30f;
#pragma unroll
        for (int na = 0; na < 8; na++) {
            mt0 = fmaxf(mt0, fmaxf(accS[na][0], accS[na][1]));
            mt1 = fmaxf(mt1, fmaxf(accS[na][2], accS[na][3]));
        }
        mt0 = fmaxf(mt0, __shfl_xor_sync(0xffffffffu, mt0, 1));
        mt0 = fmaxf(mt0, __shfl_xor_sync(0xffffffffu, mt0, 2));
        mt1 = fmaxf(mt1, __shfl_xor_sync(0xffffffffu, mt1, 1));
        mt1 = fmaxf(mt1, __shfl_xor_sync(0xffffffffu, mt1, 2));
        float mn0 = fmaxf(m0, mt0);
        float mn1 = fmaxf(m1, mt1);

        float ls0 = 0.f, ls1 = 0.f;
#pragma unroll
        for (int na = 0; na < 8; na++) {
            float p00 = (accS[na][0] < -1e29f) ? 0.f : to_tf32(__expf(accS[na][0] - mn0));
            float p01 = (accS[na][1] < -1e29f) ? 0.f : to_tf32(__expf(accS[na][1] - mn0));
            float p10 = (accS[na][2] < -1e29f) ? 0.f : to_tf32(__expf(accS[na][2] - mn1));
            float p11 = (accS[na][3] < -1e29f) ? 0.f : to_tf32(__expf(accS[na][3] - mn1));
            ls0 += p00 + p01;
            ls1 += p10 + p11;
            int c0 = na * 8 + tig * 2;
            *(float2*)(&sP[r0 * P_STRIDE + c0]) = make_float2(p00, p01);
            *(float2*)(&sP[(r0 + 8) * P_STRIDE + c0]) = make_float2(p10, p11);
        }
        ls0 += __shfl_xor_sync(0xffffffffu, ls0, 1);
        ls0 += __shfl_xor_sync(0xffffffffu, ls0, 2);
        ls1 += __shfl_xor_sync(0xffffffffu, ls1, 1);
        ls1 += __shfl_xor_sync(0xffffffffu, ls1, 2);

        float al0 = __expf(m0 - mn0);
        float al1 = __expf(m1 - mn1);
        l0 = l0 * al0 + ls0;
        l1 = l1 * al1 + ls1;
        m0 = mn0; m1 = mn1;

#pragma unroll
        for (int no = 0; no < 9; no++) {
            O[no][0] *= al0; O[no][1] *= al0;
            O[no][2] *= al1; O[no][3] *= al1;
        }
        __syncwarp();

        // ---- O += P V ----
#pragma unroll
        for (int ks = 0; ks < 8; ks++) {
            const int k0 = ks * 8;
            uint32_t a0 = uP[r0 * P_STRIDE + k0 + tig];
            uint32_t a1 = uP[(r0 + 8) * P_STRIDE + k0 + tig];
            uint32_t a2 = uP[r0 * P_STRIDE + k0 + tig + 4];
            uint32_t a3 = uP[(r0 + 8) * P_STRIDE + k0 + tig + 4];
#pragma unroll
            for (int no = 0; no < 9; no++) {
                uint32_t b0 = uV[(k0 + tig) * V_STRIDE + no * 8 + gid];
                uint32_t b1 = uV[(k0 + tig + 4) * V_STRIDE + no * 8 + gid];
                mma_tf32(O[no][0], O[no][1], O[no][2], O[no][3],
                         a0, a1, a2, a3, b0, b1);
            }
        }
        __syncthreads();
    }

    // store tf32-rounded so the O-projection GEMM can consume directly
    float il0 = 1.f / l0;
    float il1 = 1.f / l1;
    size_t ob0 = (size_t)(q0 + r0) * D_DIM + h * DH;
    size_t ob1 = (size_t)(q0 + r0 + 8) * D_DIM + h * DH;
#pragma unroll
    for (int no = 0; no < 9; no++) {
        int c0 = no * 8 + tig * 2;
        *(float2*)(out + ob0 + c0) = make_float2(to_tf32(O[no][0] * il0), to_tf32(O[no][1] * il0));
        *(float2*)(out + ob1 + c0) = make_float2(to_tf32(O[no][2] * il1), to_tf32(O[no][3] * il1));
    }
}

// ---------------- host launch ----------------
extern "C" void kernel_launch(void* const* d_in, const int* in_sizes, int n_in,
                              void* d_out, int out_size)
{
    const float* hs   = (const float*)d_in[0];
    const int*   cu   = (const int*)  d_in[1];
    const float* cosp = (const float*)d_in[2];
    const float* sinp = (const float*)d_in[3];
    const float* Wq   = (const float*)d_in[4];
    const float* bq   = (const float*)d_in[5];
    const float* Wk   = (const float*)d_in[6];
    const float* bk   = (const float*)d_in[7];
    const float* Wv   = (const float*)d_in[8];
    const float* bv   = (const float*)d_in[9];
    const float* Wo   = (const float*)d_in[10];
    const float* bo   = (const float*)d_in[11];
    float* out = (float*)d_out;

    float *q, *k, *v, *attn, *hsr, *wr;
    cudaGetSymbolAddress((void**)&q, g_q);
    cudaGetSymbolAddress((void**)&k, g_k);
    cudaGetSymbolAddress((void**)&v, g_v);
    cudaGetSymbolAddress((void**)&attn, g_attn);
    cudaGetSymbolAddress((void**)&hsr, g_hsr);
    cudaGetSymbolAddress((void**)&wr, g_wr);
    float* wqr = wr;
    float* wkr = wr + (size_t)D_DIM * D_DIM;
    float* wvr = wr + 2 * (size_t)D_DIM * D_DIM;
    float* wor = wr + 3 * (size_t)D_DIM * D_DIM;

    // pre-round hs + weights (grid x sized for the LARGEST segment: hs)
    int n4hs = T_TOK * D_DIM / 4;
    dim3 rgrid((n4hs + 255) / 256, 5);
    round_tf32_kernel<<<rgrid, 256>>>(hs, Wq, Wk, Wv, Wo);

    cudaFuncSetAttribute(gemm_cp_tf32,
                         cudaFuncAttributeMaxDynamicSharedMemorySize, GEMM_SMEM);

    // fused QKV
    dim3 qkv_grid(D_DIM / 128, T_TOK / 128, 3);
    gemm_cp_tf32<<<qkv_grid, 256, GEMM_SMEM>>>(hsr, wqr, wkr, wvr, bq, bk, bv, q, k, v);

    // attention with fused RoPE (no separate rope kernel)
    cudaFuncSetAttribute(attn_kernel,
                         cudaFuncAttributeMaxDynamicSharedMemorySize, ATTN_SMEM);
    attn_kernel<<<dim3(T_TOK / QT, H_NUM), 256, ATTN_SMEM>>>(q, k, v, cu, cosp, sinp, attn);

    // O projection
    dim3 o_grid(D_DIM / 128, T_TOK / 128, 1);
    gemm_cp_tf32<<<o_grid, 256, GEMM_SMEM>>>(attn, wor, wor, wor, bo, bo, bo, out, out, out);
}